// round 10
// baseline (speedup 1.0000x reference)
#include <cuda_runtime.h>
#include <cuda_bf16.h>
#include <cstdint>

#define NN   100000
#define NE   1600000
#define NG   64
#define DIN  128
#define HID  256
#define NB1  391          // ceil(NN/256)
#define G1BLK 148
#define NTILE1 1563       // ceil(NN/64)
#define G2BLK 125         // gemm2 split-K blocks
#define G2CH  800         // 125*800 = 100000 exactly

// ------------- static device scratch (no allocations allowed) -------------
__device__ __align__(16) __nv_bfloat16 g_xb[(size_t)NN * DIN];     // 25.6 MB
__device__ __align__(16) __nv_bfloat16 g_agg1b[(size_t)NN * DIN];  // 25.6 MB
__device__ __align__(16) __nv_bfloat16 g_h1b[(size_t)NN * HID];    // 51.2 MB
__device__ __align__(16) __nv_bfloat16 g_Wcat[2 * DIN * HID];      // 128 KB
__device__ __align__(16) float g_coef[(size_t)NN * NG];            // 25.6 MB
__device__ __align__(16) float g_Qa[NG * HID];
__device__ __align__(16) float g_P[NG * HID];
__device__ __align__(16) int g_cnt[NN];     // zero-init at load; self-restoring
__device__ int   g_eoff[NN];
__device__ int   g_wpos[NN];
__device__ int   g_bsum[NB1];
__device__ int   g_ncnt[NG];                // zero-init; self-restoring
__device__ float g_invcnt[NN];
__device__ float g_invng[NG];
__device__ __align__(8) int2 g_bg[NN];      // packed {batch, invcnt-bits}
__device__ int   g_esrc[NE];                // premultiplied: src_row * 16 (uint4 units)
__device__ int   g_barc;                    // grid barrier ctr; reset by place_k

// --------------------------- helpers ---------------------------
__device__ __forceinline__ uint32_t pkbf(float lo, float hi) {
    __nv_bfloat162 h = __float22bfloat162_rn(make_float2(lo, hi));
    return *(uint32_t*)&h;
}
__device__ __forceinline__ uint32_t s2u(const void* p) {
    return (uint32_t)__cvta_generic_to_shared(p);
}
__device__ __forceinline__ void ldmA(uint32_t r[4], uint32_t addr) {
    asm volatile("ldmatrix.sync.aligned.m8n8.x4.shared.b16 {%0,%1,%2,%3}, [%4];"
                 : "=r"(r[0]), "=r"(r[1]), "=r"(r[2]), "=r"(r[3]) : "r"(addr));
}
__device__ __forceinline__ void ldmT(uint32_t r[4], uint32_t addr) {
    asm volatile("ldmatrix.sync.aligned.m8n8.x4.trans.shared.b16 {%0,%1,%2,%3}, [%4];"
                 : "=r"(r[0]), "=r"(r[1]), "=r"(r[2]), "=r"(r[3]) : "r"(addr));
}
__device__ __forceinline__ void mma16816(float c[4], const uint32_t a[4], const uint32_t b[2]) {
    asm volatile("mma.sync.aligned.m16n8k16.row.col.f32.bf16.bf16.f32 "
                 "{%0,%1,%2,%3}, {%4,%5,%6,%7}, {%8,%9}, {%0,%1,%2,%3};"
                 : "+f"(c[0]), "+f"(c[1]), "+f"(c[2]), "+f"(c[3])
                 : "r"(a[0]), "r"(a[1]), "r"(a[2]), "r"(a[3]), "r"(b[0]), "r"(b[1]));
}
#define EXPADD(tx, acc)                                                          \
    {                                                                            \
        unsigned long long v2 = ((unsigned long long)((tx) & 0xFFFF0000u) << 32) \
                              | (unsigned long long)((tx) << 16);                \
        asm("add.rn.f32x2 %0, %0, %1;" : "+l"(acc) : "l"(v2));                   \
    }
#define MERGE16(acc)                                                             \
    {                                                                            \
        unsigned long long o = __shfl_down_sync(0xffffffffu, (acc), 16);         \
        asm("add.rn.f32x2 %0, %0, %1;" : "+l"(acc) : "l"(o));                    \
    }

// ------- initA: convert x, build Wcat, zero coef/Qa/P -------
__global__ void initA_k(const float* __restrict__ x,
                        const float* __restrict__ W1l, const float* __restrict__ W1r) {
    size_t i = (size_t)blockIdx.x * blockDim.x + threadIdx.x;
    size_t stride = (size_t)gridDim.x * blockDim.x;
    float4 z = make_float4(0.f, 0.f, 0.f, 0.f);
    for (size_t j = i; j < (size_t)NN * NG / 4; j += stride)
        ((float4*)g_coef)[j] = z;
    for (size_t j = i; j < NG * HID / 4; j += stride) {
        ((float4*)g_Qa)[j] = z;
        ((float4*)g_P)[j] = z;
    }
    for (size_t j = i; j < (size_t)NN * DIN / 4; j += stride) {
        float4 v = ((const float4*)x)[j];
        ((uint2*)g_xb)[j] = make_uint2(pkbf(v.x, v.y), pkbf(v.z, v.w));
    }
    for (size_t j = i; j < (size_t)2 * DIN * HID / 4; j += stride) {
        size_t e = j * 4;
        int k = (int)(e >> 8), n = (int)(e & 255);
        const float* src = (k < DIN) ? &W1r[k * HID + n] : &W1l[(k - DIN) * HID + n];
        float4 v = *(const float4*)src;
        ((uint2*)g_Wcat)[j] = make_uint2(pkbf(v.x, v.y), pkbf(v.z, v.w));
    }
}

// ---------------- degree count + per-graph node count (fused, int4) ----------------
__global__ void cnt_k(const int* __restrict__ ei, const int* __restrict__ batch) {
    int i = blockIdx.x * blockDim.x + threadIdx.x;
    int stride = gridDim.x * blockDim.x;
    const int4* d4 = (const int4*)(ei + NE);
    for (int j = i; j < NE / 4; j += stride) {
        int4 d = d4[j];
        atomicAdd(&g_cnt[d.x], 1);
        atomicAdd(&g_cnt[d.y], 1);
        atomicAdd(&g_cnt[d.z], 1);
        atomicAdd(&g_cnt[d.w], 1);
    }
    const int4* b4 = (const int4*)batch;
    for (int j = i; j < NN / 4; j += stride) {
        int4 b = b4[j];
        if (b.x == b.w) {
            atomicAdd(&g_ncnt[b.x], 4);
        } else {
            atomicAdd(&g_ncnt[b.x], 1);
            atomicAdd(&g_ncnt[b.y], 1);
            atomicAdd(&g_ncnt[b.z], 1);
            atomicAdd(&g_ncnt[b.w], 1);
        }
    }
}

// ------- scanF: full exclusive scan + finalize, one launch (grid barrier) -------
// Also self-restores g_cnt/g_ncnt to zero for the next replay.
__global__ void __launch_bounds__(256) scanF_k(const int* __restrict__ batch) {
    __shared__ int sh[256];
    __shared__ int red[256];
    int t = threadIdx.x;
    int b = blockIdx.x;
    int i = b * 256 + t;

    // phase 1: per-chunk inclusive scan
    int val = (i < NN) ? g_cnt[i] : 0;
    sh[t] = val;
    __syncthreads();
    for (int d = 1; d < 256; d <<= 1) {
        int add = (t >= d) ? sh[t - d] : 0;
        __syncthreads();
        sh[t] += add;
        __syncthreads();
    }
    int local_excl = sh[t] - val;
    if (t == 255) g_bsum[b] = sh[255];

    // grid barrier
    __syncthreads();
    if (t == 0) {
        __threadfence();
        atomicAdd(&g_barc, 1);
        while (*(volatile int*)&g_barc < NB1) { }
        __threadfence();
    }
    __syncthreads();

    // phase 2: block-prefix of bsum + finalize
    int part = 0;
    for (int j = t; j < b; j += 256) part += g_bsum[j];
    red[t] = part;
    __syncthreads();
    for (int s = 128; s > 0; s >>= 1) {
        if (t < s) red[t] += red[t + s];
        __syncthreads();
    }
    int boff = red[0];
    if (i < NN) {
        int off = local_excl + boff;
        g_eoff[i] = off;
        g_wpos[i] = off;
        float ic = 1.0f / fmaxf((float)val, 1.0f);
        g_invcnt[i] = ic;
        g_bg[i] = make_int2(batch[i], __float_as_int(ic));
        g_cnt[i] = 0;                       // restore for next replay
    }
    if (i < NG) {
        g_invng[i] = 1.0f / fmaxf((float)g_ncnt[i], 1.0f);
        g_ncnt[i] = 0;                      // restore for next replay
    }
}

// ------- coef_k (forked stream): coef[s][batch[d]] += invcnt[d] -------
__global__ void coef_k(const int* __restrict__ ei) {
    int t = blockIdx.x * blockDim.x + threadIdx.x;
    if (t < NE / 4) {
        int4 s4 = ((const int4*)ei)[t];
        int4 d4 = ((const int4*)(ei + NE))[t];
#define CEDGE(s, d)                                                     \
        {                                                               \
            int2 bg = g_bg[(d)];                                        \
            atomicAdd(&g_coef[(s) * NG + bg.x], __int_as_float(bg.y));  \
        }
        CEDGE(s4.x, d4.x)
        CEDGE(s4.y, d4.y)
        CEDGE(s4.z, d4.z)
        CEDGE(s4.w, d4.w)
#undef CEDGE
    }
}

// ------- place_k: CSR bucket placement (premultiplied uint4 offsets) -------
__global__ void place_k(const int* __restrict__ ei) {
    int t = blockIdx.x * blockDim.x + threadIdx.x;
    if (t == 0) g_barc = 0;                 // reset grid-barrier for next replay
    if (t < NE / 4) {
        int4 s4 = ((const int4*)ei)[t];
        int4 d4 = ((const int4*)(ei + NE))[t];
#define PEDGE(s, d)                                   \
        {                                             \
            int p = atomicAdd(&g_wpos[(d)], 1);       \
            g_esrc[p] = (s) * (DIN / 8);              \
        }
        PEDGE(s4.x, d4.x)
        PEDGE(s4.y, d4.y)
        PEDGE(s4.z, d4.z)
        PEDGE(s4.w, d4.w)
#undef PEDGE
    }
}

// ------- layer-1 mean aggregation: warp/node, half-warp per edge (uint4) -------
__global__ void agg1_k() {
    int gtid = blockIdx.x * blockDim.x + threadIdx.x;
    int v = gtid >> 5;
    if (v >= NN) return;
    int lane = gtid & 31;
    int sub = lane >> 4;       // which edge of the pair
    int lpos = lane & 15;      // uint4 position within the 256B row
    int start = g_eoff[v];
    int end = (v + 1 < NN) ? g_eoff[v + 1] : NE;
    unsigned long long a01 = 0ull, a23 = 0ull, a45 = 0ull, a67 = 0ull;
    const uint4* xb4 = (const uint4*)g_xb;
    int i = start;
    for (; i + 2 <= end; i += 2) {
        int o = g_esrc[i + sub];
        uint4 t = xb4[o + lpos];
        EXPADD(t.x, a01) EXPADD(t.y, a23) EXPADD(t.z, a45) EXPADD(t.w, a67)
    }
    if (i < end && sub == 0) {
        int o = g_esrc[i];
        uint4 t = xb4[o + lpos];
        EXPADD(t.x, a01) EXPADD(t.y, a23) EXPADD(t.z, a45) EXPADD(t.w, a67)
    }
    MERGE16(a01) MERGE16(a23) MERGE16(a45) MERGE16(a67)
    if (sub == 0) {
        float w = g_invcnt[v];
        float f0 = __uint_as_float((uint32_t)a01) * w;
        float f1 = __uint_as_float((uint32_t)(a01 >> 32)) * w;
        float f2 = __uint_as_float((uint32_t)a23) * w;
        float f3 = __uint_as_float((uint32_t)(a23 >> 32)) * w;
        float f4 = __uint_as_float((uint32_t)a45) * w;
        float f5 = __uint_as_float((uint32_t)(a45 >> 32)) * w;
        float f6 = __uint_as_float((uint32_t)a67) * w;
        float f7 = __uint_as_float((uint32_t)(a67 >> 32)) * w;
        ((uint4*)g_agg1b)[v * (DIN / 8) + lpos] =
            make_uint4(pkbf(f0, f1), pkbf(f2, f3), pkbf(f4, f5), pkbf(f6, f7));
    }
}

// ----------- GEMM1 (persistent, Wcat resident in smem): h1 = relu([x|agg1]@Wcat + b1) -----------
__global__ void __launch_bounds__(256) gemm1_k(const float* __restrict__ b1) {
    extern __shared__ __nv_bfloat16 sm1[];
    __nv_bfloat16* Bs = sm1;                 // 256 x 264
    __nv_bfloat16* As = sm1 + 256 * 264;     // 64 x 264
    int tid = threadIdx.x;
    int wid = tid >> 5, lane = tid & 31;
    int mw = (wid & 1) * 32;
    int nw = (wid >> 1) * 64;

    for (int j = tid; j < 256 * 32; j += 256) {
        int row = j >> 5, col = (j & 31) * 8;
        *(uint4*)&Bs[row * 264 + col] = *(const uint4*)&g_Wcat[(size_t)row * HID + col];
    }

    uint4 pa[8];
    int ti = blockIdx.x;

    if (ti < NTILE1) {
#pragma unroll
        for (int j = 0; j < 8; j++) {
            int idx = tid + j * 256;
            int row = idx >> 5, col = (idx & 31) * 8;
            int gr = ti * 64 + row;
            if (gr < NN) {
                const __nv_bfloat16* src = (col < DIN) ? &g_xb[(size_t)gr * DIN + col]
                                                       : &g_agg1b[(size_t)gr * DIN + (col - DIN)];
                pa[j] = *(const uint4*)src;
            } else pa[j] = make_uint4(0, 0, 0, 0);
        }
    }

    for (; ti < NTILE1; ti += G1BLK) {
        __syncthreads();
#pragma unroll
        for (int j = 0; j < 8; j++) {
            int idx = tid + j * 256;
            int row = idx >> 5, col = (idx & 31) * 8;
            *(uint4*)&As[row * 264 + col] = pa[j];
        }
        __syncthreads();

        int tn = ti + G1BLK;
        if (tn < NTILE1) {
#pragma unroll
            for (int j = 0; j < 8; j++) {
                int idx = tid + j * 256;
                int row = idx >> 5, col = (idx & 31) * 8;
                int gr = tn * 64 + row;
                if (gr < NN) {
                    const __nv_bfloat16* src = (col < DIN) ? &g_xb[(size_t)gr * DIN + col]
                                                           : &g_agg1b[(size_t)gr * DIN + (col - DIN)];
                    pa[j] = *(const uint4*)src;
                } else pa[j] = make_uint4(0, 0, 0, 0);
            }
        }

        float acc[2][8][4];
#pragma unroll
        for (int i = 0; i < 2; i++)
#pragma unroll
            for (int j = 0; j < 8; j++)
#pragma unroll
                for (int q = 0; q < 4; q++) acc[i][j][q] = 0.f;

#pragma unroll
        for (int ks = 0; ks < 256; ks += 16) {
            uint32_t af[2][4];
#pragma unroll
            for (int mi = 0; mi < 2; mi++) {
                uint32_t addr = s2u(&As[(mw + mi * 16 + (lane & 15)) * 264 + ks + (lane >> 4) * 8]);
                ldmA(af[mi], addr);
            }
#pragma unroll
            for (int nf = 0; nf < 4; nf++) {
                uint32_t bf[4];
                uint32_t addr = s2u(&Bs[(ks + ((lane >> 3) & 1) * 8 + (lane & 7)) * 264 +
                                        nw + nf * 16 + (lane >> 4) * 8]);
                ldmT(bf, addr);
#pragma unroll
                for (int mi = 0; mi < 2; mi++) {
                    mma16816(acc[mi][nf * 2], af[mi], bf);
                    mma16816(acc[mi][nf * 2 + 1], af[mi], bf + 2);
                }
            }
        }

        int m0 = ti * 64;
        uint32_t* h1u = (uint32_t*)g_h1b;
#pragma unroll
        for (int mi = 0; mi < 2; mi++) {
#pragma unroll
            for (int nf = 0; nf < 8; nf++) {
                int col = nw + nf * 8 + (lane & 3) * 2;
                float bx = b1[col], by = b1[col + 1];
                int row = m0 + mw + mi * 16 + (lane >> 2);
                if (row < NN)
                    h1u[((size_t)row * HID + col) >> 1] =
                        pkbf(fmaxf(acc[mi][nf][0] + bx, 0.f), fmaxf(acc[mi][nf][1] + by, 0.f));
                int row2 = row + 8;
                if (row2 < NN)
                    h1u[((size_t)row2 * HID + col) >> 1] =
                        pkbf(fmaxf(acc[mi][nf][2] + bx, 0.f), fmaxf(acc[mi][nf][3] + by, 0.f));
            }
        }
    }
}

// ------- GEMM2 (bf16 mma) + fused pool: Qa = coef^T @ h1, P = segsum(h1) -------
__global__ void __launch_bounds__(256) gemm2_k(const int* __restrict__ batch) {
    __shared__ __align__(16) __nv_bfloat16 Ks[32 * 72];
    __shared__ __align__(16) __nv_bfloat16 Bs[32 * 264];
    __shared__ int sbatch[32];
    int tid = threadIdx.x;
    int wid = tid >> 5, lane = tid & 31;
    int nb = blockIdx.x * G2CH;
    int n0w = wid * 32;

    float acc[4][4][4];
#pragma unroll
    for (int i = 0; i < 4; i++)
#pragma unroll
        for (int j = 0; j < 4; j++)
#pragma unroll
            for (int q = 0; q < 4; q++) acc[i][j][q] = 0.f;

    int cnode = tid >> 3;
    int cg = (tid & 7) * 8;

    float4 cf0, cf1;
    uint4 hb[4];

    {
        size_t base = (size_t)(nb + cnode) * NG + cg;
        cf0 = *(const float4*)&g_coef[base];
        cf1 = *(const float4*)&g_coef[base + 4];
#pragma unroll
        for (int j = 0; j < 4; j++) {
            int c = tid + 256 * j;
            int row = c >> 5, col = (c & 31) * 8;
            hb[j] = *(const uint4*)&g_h1b[(size_t)(nb + row) * HID + col];
        }
    }

    int curg = batch[nb];
    float psum = 0.f;

    for (int s = 0; s < 25; s++) {
        __syncthreads();
        {
            uint4 kv = make_uint4(pkbf(cf0.x, cf0.y), pkbf(cf0.z, cf0.w),
                                  pkbf(cf1.x, cf1.y), pkbf(cf1.z, cf1.w));
            *(uint4*)&Ks[cnode * 72 + cg] = kv;
#pragma unroll
            for (int j = 0; j < 4; j++) {
                int c = tid + 256 * j;
                int row = c >> 5, col = (c & 31) * 8;
                *(uint4*)&Bs[row * 264 + col] = hb[j];
            }
            if (tid < 32) sbatch[tid] = batch[nb + s * 32 + tid];
        }
        __syncthreads();

        if (s + 1 < 25) {
            int kb = nb + (s + 1) * 32;
            size_t base = (size_t)(kb + cnode) * NG + cg;
            cf0 = *(const float4*)&g_coef[base];
            cf1 = *(const float4*)&g_coef[base + 4];
#pragma unroll
            for (int j = 0; j < 4; j++) {
                int c = tid + 256 * j;
                int row = c >> 5, col = (c & 31) * 8;
                hb[j] = *(const uint4*)&g_h1b[(size_t)(kb + row) * HID + col];
            }
        }

#pragma unroll
        for (int ks = 0; ks < 32; ks += 16) {
            uint32_t af[4][4];
#pragma unroll
            for (int mi = 0; mi < 4; mi++) {
                uint32_t addr = s2u(&Ks[(ks + ((lane >> 4) & 1) * 8 + (lane & 7)) * 72 +
                                        mi * 16 + ((lane >> 3) & 1) * 8]);
                ldmT(af[mi], addr);
            }
#pragma unroll
            for (int nf = 0; nf < 2; nf++) {
                uint32_t bf[4];
                uint32_t addr = s2u(&Bs[(ks + ((lane >> 3) & 1) * 8 + (lane & 7)) * 264 +
                                        n0w + nf * 16 + (lane >> 4) * 8]);
                ldmT(bf, addr);
#pragma unroll
                for (int mi = 0; mi < 4; mi++) {
                    mma16816(acc[mi][nf * 2], af[mi], bf);
                    mma16816(acc[mi][nf * 2 + 1], af[mi], bf + 2);
                }
            }
        }

        for (int r = 0; r < 32; r++) {
            int g = sbatch[r];
            float v = __bfloat162float(Bs[r * 264 + tid]);
            if (g != curg) {
                atomicAdd(&g_P[curg * HID + tid], psum);
                psum = 0.f;
                curg = g;
            }
            psum += v;
        }
    }
    atomicAdd(&g_P[curg * HID + tid], psum);

#pragma unroll
    for (int mi = 0; mi < 4; mi++) {
#pragma unroll
        for (int nf = 0; nf < 4; nf++) {
            int col = n0w + nf * 8 + (lane & 3) * 2;
            int row = mi * 16 + (lane >> 2);
            atomicAdd(&g_Qa[row * HID + col], acc[mi][nf][0]);
            atomicAdd(&g_Qa[row * HID + col + 1], acc[mi][nf][1]);
            atomicAdd(&g_Qa[(row + 8) * HID + col], acc[mi][nf][2]);
            atomicAdd(&g_Qa[(row + 8) * HID + col + 1], acc[mi][nf][3]);
        }
    }
}

// --------------------------- final: layer2 fold + pool + MLP head ---------------------------
__global__ void final_k(const float* __restrict__ gattr,
                        const float* __restrict__ W2l, const float* __restrict__ b2,
                        const float* __restrict__ W2r,
                        const float* __restrict__ Wf1, const float* __restrict__ bf1,
                        const float* __restrict__ Wf2, const float* __restrict__ bf2,
                        float* __restrict__ out) {
    __shared__ float q[HID], p[HID], pooled[HID], red[HID];
    int g = blockIdx.x, j = threadIdx.x;
    q[j] = g_Qa[g * HID + j];
    p[j] = g_P[g * HID + j];
    __syncthreads();
    float acc = 0.f;
    for (int k = 0; k < HID; k++)
        acc += q[k] * W2l[k * HID + j] + p[k] * W2r[k * HID + j];
    pooled[j] = g_invng[g] * acc + b2[j];
    __syncthreads();
    float a2 = bf1[j];
    for (int k = 0; k < HID; k++)
        a2 += pooled[k] * Wf1[k * HID + j];
    for (int a = 0; a < 8; a++)
        a2 += gattr[g * 8 + a] * Wf1[(HID + a) * HID + j];
    float t1 = fmaxf(a2, 0.f);
    red[j] = t1 * Wf2[j];
    __syncthreads();
    for (int s = 128; s > 0; s >>= 1) {
        if (j < s) red[j] += red[j + s];
        __syncthreads();
    }
    if (j == 0) out[g] = red[0] + bf2[0];
}

// --------------------------- launch ---------------------------
extern "C" void kernel_launch(void* const* d_in, const int* in_sizes, int n_in,
                              void* d_out, int out_size) {
    const float* x = (const float*)d_in[0];
    const int* ei = (const int*)d_in[1];
    const int* batch = (const int*)d_in[2];
    const float* gattr = (const float*)d_in[3];
    const float* W1l = (const float*)d_in[4];
    const float* b1  = (const float*)d_in[5];
    const float* W1r = (const float*)d_in[6];
    const float* W2l = (const float*)d_in[7];
    const float* b2  = (const float*)d_in[8];
    const float* W2r = (const float*)d_in[9];
    const float* Wf1 = (const float*)d_in[10];
    const float* bf1 = (const float*)d_in[11];
    const float* Wf2 = (const float*)d_in[12];
    const float* bf2 = (const float*)d_in[13];
    float* out = (float*)d_out;

    static cudaStream_t sA = nullptr;
    static cudaEvent_t evFork = nullptr, evJoin = nullptr;
    if (sA == nullptr) {
        cudaStreamCreateWithFlags(&sA, cudaStreamNonBlocking);
        cudaEventCreateWithFlags(&evFork, cudaEventDisableTiming);
        cudaEventCreateWithFlags(&evJoin, cudaEventDisableTiming);
        const int S = (256 * 264 + 64 * 264) * (int)sizeof(__nv_bfloat16);
        cudaFuncSetAttribute(gemm1_k, cudaFuncAttributeMaxDynamicSharedMemorySize, S);
    }
    const int SMEM1 = (256 * 264 + 64 * 264) * (int)sizeof(__nv_bfloat16);  // 168960 B

    initA_k<<<1024, 256>>>(x, W1l, W1r);
    cnt_k<<<1563, 256>>>(ei, batch);
    scanF_k<<<NB1, 256>>>(batch);

    // fork: coef atomics (L2-bound) overlap place/agg1/gemm1 (issue/tensor-bound)
    cudaEventRecord(evFork, 0);
    cudaStreamWaitEvent(sA, evFork, 0);
    coef_k<<<(NE / 4 + 255) / 256, 256, 0, sA>>>(ei);      // 4th issue -> ncu sample
    cudaEventRecord(evJoin, sA);

    place_k<<<(NE / 4 + 255) / 256, 256>>>(ei);
    agg1_k<<<(NN * 32 + 255) / 256, 256>>>();
    gemm1_k<<<G1BLK, 256, SMEM1>>>(b1);

    cudaStreamWaitEvent(0, evJoin, 0);
    gemm2_k<<<G2BLK, 256>>>(batch);
    final_k<<<NG, 256>>>(gattr, W2l, b2, W2r, Wf1, bf1, Wf2, bf2, out);
}

// round 11
// speedup vs baseline: 1.0543x; 1.0543x over previous
#include <cuda_runtime.h>
#include <cuda_bf16.h>
#include <cstdint>

#define NN   100000
#define NE   1600000
#define NG   64
#define DIN  128
#define HID  256
#define NB1  391          // ceil(NN/256)
#define G1BLK 148
#define NTILE1 1563       // ceil(NN/64)
#define G2BLK 125         // gemm2 split-K blocks
#define G2CH  800         // 125*800 = 100000 exactly

// ------------- static device scratch (no allocations allowed) -------------
__device__ __align__(16) __nv_bfloat16 g_xb[(size_t)NN * DIN];     // 25.6 MB
__device__ __align__(16) __nv_bfloat16 g_agg1b[(size_t)NN * DIN];  // 25.6 MB
__device__ __align__(16) __nv_bfloat16 g_h1b[(size_t)NN * HID];    // 51.2 MB
__device__ __align__(16) __nv_bfloat16 g_Wcat[2 * DIN * HID];      // 128 KB
__device__ __align__(16) float g_coef[(size_t)NN * NG];            // 25.6 MB
__device__ __align__(16) float g_Qa[NG * HID];
__device__ __align__(16) float g_P[NG * HID];
__device__ __align__(16) int g_cnt[NN];
__device__ int   g_eoff[NN];
__device__ int   g_wpos[NN];
__device__ int   g_bsum[NB1];
__device__ int   g_ncnt[NG];
__device__ float g_invcnt[NN];
__device__ float g_invng[NG];
__device__ __align__(8) int2 g_bg[NN];     // packed {batch, invcnt-bits}
__device__ int   g_esrc[NE];               // premultiplied: src_row * 32 (uint2 units)

// --------------------------- helpers ---------------------------
__device__ __forceinline__ uint32_t pkbf(float lo, float hi) {
    __nv_bfloat162 h = __float22bfloat162_rn(make_float2(lo, hi));
    return *(uint32_t*)&h;
}
__device__ __forceinline__ uint32_t s2u(const void* p) {
    return (uint32_t)__cvta_generic_to_shared(p);
}
__device__ __forceinline__ void ldmA(uint32_t r[4], uint32_t addr) {
    asm volatile("ldmatrix.sync.aligned.m8n8.x4.shared.b16 {%0,%1,%2,%3}, [%4];"
                 : "=r"(r[0]), "=r"(r[1]), "=r"(r[2]), "=r"(r[3]) : "r"(addr));
}
__device__ __forceinline__ void ldmT(uint32_t r[4], uint32_t addr) {
    asm volatile("ldmatrix.sync.aligned.m8n8.x4.trans.shared.b16 {%0,%1,%2,%3}, [%4];"
                 : "=r"(r[0]), "=r"(r[1]), "=r"(r[2]), "=r"(r[3]) : "r"(addr));
}
__device__ __forceinline__ void mma16816(float c[4], const uint32_t a[4], const uint32_t b[2]) {
    asm volatile("mma.sync.aligned.m16n8k16.row.col.f32.bf16.bf16.f32 "
                 "{%0,%1,%2,%3}, {%4,%5,%6,%7}, {%8,%9}, {%0,%1,%2,%3};"
                 : "+f"(c[0]), "+f"(c[1]), "+f"(c[2]), "+f"(c[3])
                 : "r"(a[0]), "r"(a[1]), "r"(a[2]), "r"(a[3]), "r"(b[0]), "r"(b[1]));
}

// ------- initA: convert x, build Wcat, zero coef/Qa/P -------
__global__ void initA_k(const float* __restrict__ x,
                        const float* __restrict__ W1l, const float* __restrict__ W1r) {
    size_t i = (size_t)blockIdx.x * blockDim.x + threadIdx.x;
    size_t stride = (size_t)gridDim.x * blockDim.x;
    float4 z = make_float4(0.f, 0.f, 0.f, 0.f);
    for (size_t j = i; j < (size_t)NN * NG / 4; j += stride)
        ((float4*)g_coef)[j] = z;
    for (size_t j = i; j < NG * HID / 4; j += stride) {
        ((float4*)g_Qa)[j] = z;
        ((float4*)g_P)[j] = z;
    }
    for (size_t j = i; j < (size_t)NN * DIN / 4; j += stride) {
        float4 v = ((const float4*)x)[j];
        ((uint2*)g_xb)[j] = make_uint2(pkbf(v.x, v.y), pkbf(v.z, v.w));
    }
    for (size_t j = i; j < (size_t)2 * DIN * HID / 4; j += stride) {
        size_t e = j * 4;
        int k = (int)(e >> 8), n = (int)(e & 255);
        const float* src = (k < DIN) ? &W1r[k * HID + n] : &W1l[(k - DIN) * HID + n];
        float4 v = *(const float4*)src;
        ((uint2*)g_Wcat)[j] = make_uint2(pkbf(v.x, v.y), pkbf(v.z, v.w));
    }
}

// ------- initB: zero the counters the count pass needs -------
__global__ void initB_k() {
    int i = blockIdx.x * blockDim.x + threadIdx.x;
    int stride = gridDim.x * blockDim.x;
    for (int j = i; j < NN / 4; j += stride)
        ((int4*)g_cnt)[j] = make_int4(0, 0, 0, 0);
    if (i < NG) g_ncnt[i] = 0;
}

// ---------------- degree count + per-graph node count (fused, int4) ----------------
__global__ void cnt_k(const int* __restrict__ ei, const int* __restrict__ batch) {
    int i = blockIdx.x * blockDim.x + threadIdx.x;
    int stride = gridDim.x * blockDim.x;
    const int4* d4 = (const int4*)(ei + NE);
    for (int j = i; j < NE / 4; j += stride) {
        int4 d = d4[j];
        atomicAdd(&g_cnt[d.x], 1);
        atomicAdd(&g_cnt[d.y], 1);
        atomicAdd(&g_cnt[d.z], 1);
        atomicAdd(&g_cnt[d.w], 1);
    }
    const int4* b4 = (const int4*)batch;
    for (int j = i; j < NN / 4; j += stride) {
        int4 b = b4[j];
        if (b.x == b.w) {
            atomicAdd(&g_ncnt[b.x], 4);
        } else {
            atomicAdd(&g_ncnt[b.x], 1);
            atomicAdd(&g_ncnt[b.y], 1);
            atomicAdd(&g_ncnt[b.z], 1);
            atomicAdd(&g_ncnt[b.w], 1);
        }
    }
}

// --------------------------- scan stage 1: per-256-chunk ---------------------------
__global__ void scan1_k() {
    __shared__ int sh[256];
    int t = threadIdx.x;
    int i = blockIdx.x * 256 + t;
    int val = (i < NN) ? g_cnt[i] : 0;
    sh[t] = val;
    __syncthreads();
    for (int d = 1; d < 256; d <<= 1) {
        int add = (t >= d) ? sh[t - d] : 0;
        __syncthreads();
        sh[t] += add;
        __syncthreads();
    }
    if (i < NN) g_eoff[i] = sh[t] - val;
    if (t == 255) g_bsum[blockIdx.x] = sh[255];
}

// ------- scan stage 2+3 merged: each block re-reduces bsum prefix, finalizes -------
__global__ void scan23_k(const int* __restrict__ batch) {
    __shared__ int red[256];
    int t = threadIdx.x;
    int b = blockIdx.x;
    int part = 0;
    for (int i = t; i < b; i += 256) part += g_bsum[i];
    red[t] = part;
    __syncthreads();
    for (int s = 128; s > 0; s >>= 1) {
        if (t < s) red[t] += red[t + s];
        __syncthreads();
    }
    int boff = red[0];
    int i = b * 256 + t;
    if (i < NN) {
        int off = g_eoff[i] + boff;
        g_eoff[i] = off;
        g_wpos[i] = off;
        float ic = 1.0f / fmaxf((float)g_cnt[i], 1.0f);
        g_invcnt[i] = ic;
        g_bg[i] = make_int2(batch[i], __float_as_int(ic));
    }
    if (i < NG) g_invng[i] = 1.0f / fmaxf((float)g_ncnt[i], 1.0f);
}

// ------- place_k: CSR bucket placement (critical path) -------
__global__ void place_k(const int* __restrict__ ei) {
    int t = blockIdx.x * blockDim.x + threadIdx.x;
    if (t < NE / 4) {
        int4 s4 = ((const int4*)ei)[t];
        int4 d4 = ((const int4*)(ei + NE))[t];
#define PEDGE(s, d)                                   \
        {                                             \
            int p = atomicAdd(&g_wpos[(d)], 1);       \
            g_esrc[p] = (s) * (DIN / 4);              \
        }
        PEDGE(s4.x, d4.x)
        PEDGE(s4.y, d4.y)
        PEDGE(s4.z, d4.z)
        PEDGE(s4.w, d4.w)
#undef PEDGE
    }
}

// ------- coef_k (forked stream, overlaps agg1+gemm1): coef[s][batch[d]] += invcnt[d] -------
__global__ void coef_k(const int* __restrict__ ei) {
    int t = blockIdx.x * blockDim.x + threadIdx.x;
    if (t < NE / 4) {
        int4 s4 = ((const int4*)ei)[t];
        int4 d4 = ((const int4*)(ei + NE))[t];
#define CEDGE(s, d)                                                     \
        {                                                               \
            int2 bg = g_bg[(d)];                                        \
            atomicAdd(&g_coef[(s) * NG + bg.x], __int_as_float(bg.y));  \
        }
        CEDGE(s4.x, d4.x)
        CEDGE(s4.y, d4.y)
        CEDGE(s4.z, d4.z)
        CEDGE(s4.w, d4.w)
#undef CEDGE
    }
}

// ------- layer-1 mean aggregation (warp/node, premult offsets, f32x2 packed adds) -------
__global__ void agg1_k() {
    int gtid = blockIdx.x * blockDim.x + threadIdx.x;
    int v = gtid >> 5;
    if (v >= NN) return;
    int lane = gtid & 31;
    int start = g_eoff[v];
    int end = (v + 1 < NN) ? g_eoff[v + 1] : NE;
    unsigned long long a01 = 0ull, a23 = 0ull;   // packed (f32,f32)
    const uint2* xb2 = (const uint2*)g_xb;
#define EXPADD(tx, acc)                                                          \
    {                                                                            \
        unsigned long long v2 = ((unsigned long long)((tx) & 0xFFFF0000u) << 32) \
                              | (unsigned long long)((tx) << 16);                \
        asm("add.rn.f32x2 %0, %0, %1;" : "+l"(acc) : "l"(v2));                   \
    }
    int i = start;
    for (; i + 4 <= end; i += 4) {
        int o0 = g_esrc[i], o1 = g_esrc[i + 1], o2 = g_esrc[i + 2], o3 = g_esrc[i + 3];
        uint2 t0 = xb2[o0 + lane];
        uint2 t1 = xb2[o1 + lane];
        uint2 t2 = xb2[o2 + lane];
        uint2 t3 = xb2[o3 + lane];
        EXPADD(t0.x, a01) EXPADD(t0.y, a23)
        EXPADD(t1.x, a01) EXPADD(t1.y, a23)
        EXPADD(t2.x, a01) EXPADD(t2.y, a23)
        EXPADD(t3.x, a01) EXPADD(t3.y, a23)
    }
    for (; i < end; ++i) {
        uint2 t = xb2[g_esrc[i] + lane];
        EXPADD(t.x, a01) EXPADD(t.y, a23)
    }
#undef EXPADD
    float w = g_invcnt[v];
    float f0 = __uint_as_float((uint32_t)a01) * w;
    float f1 = __uint_as_float((uint32_t)(a01 >> 32)) * w;
    float f2 = __uint_as_float((uint32_t)a23) * w;
    float f3 = __uint_as_float((uint32_t)(a23 >> 32)) * w;
    ((uint2*)g_agg1b)[v * (DIN / 4) + lane] = make_uint2(pkbf(f0, f1), pkbf(f2, f3));
}

// ----------- GEMM1 (persistent, Wcat resident in smem): h1 = relu([x|agg1]@Wcat + b1) -----------
__global__ void __launch_bounds__(256) gemm1_k(const float* __restrict__ b1) {
    extern __shared__ __nv_bfloat16 sm1[];
    __nv_bfloat16* Bs = sm1;                 // 256 x 264
    __nv_bfloat16* As = sm1 + 256 * 264;     // 64 x 264
    int tid = threadIdx.x;
    int wid = tid >> 5, lane = tid & 31;
    int mw = (wid & 1) * 32;
    int nw = (wid >> 1) * 64;

    for (int j = tid; j < 256 * 32; j += 256) {
        int row = j >> 5, col = (j & 31) * 8;
        *(uint4*)&Bs[row * 264 + col] = *(const uint4*)&g_Wcat[(size_t)row * HID + col];
    }

    uint4 pa[8];
    int ti = blockIdx.x;

    if (ti < NTILE1) {
#pragma unroll
        for (int j = 0; j < 8; j++) {
            int idx = tid + j * 256;
            int row = idx >> 5, col = (idx & 31) * 8;
            int gr = ti * 64 + row;
            if (gr < NN) {
                const __nv_bfloat16* src = (col < DIN) ? &g_xb[(size_t)gr * DIN + col]
                                                       : &g_agg1b[(size_t)gr * DIN + (col - DIN)];
                pa[j] = *(const uint4*)src;
            } else pa[j] = make_uint4(0, 0, 0, 0);
        }
    }

    for (; ti < NTILE1; ti += G1BLK) {
        __syncthreads();
#pragma unroll
        for (int j = 0; j < 8; j++) {
            int idx = tid + j * 256;
            int row = idx >> 5, col = (idx & 31) * 8;
            *(uint4*)&As[row * 264 + col] = pa[j];
        }
        __syncthreads();

        int tn = ti + G1BLK;
        if (tn < NTILE1) {
#pragma unroll
            for (int j = 0; j < 8; j++) {
                int idx = tid + j * 256;
                int row = idx >> 5, col = (idx & 31) * 8;
                int gr = tn * 64 + row;
                if (gr < NN) {
                    const __nv_bfloat16* src = (col < DIN) ? &g_xb[(size_t)gr * DIN + col]
                                                           : &g_agg1b[(size_t)gr * DIN + (col - DIN)];
                    pa[j] = *(const uint4*)src;
                } else pa[j] = make_uint4(0, 0, 0, 0);
            }
        }

        float acc[2][8][4];
#pragma unroll
        for (int i = 0; i < 2; i++)
#pragma unroll
            for (int j = 0; j < 8; j++)
#pragma unroll
                for (int q = 0; q < 4; q++) acc[i][j][q] = 0.f;

#pragma unroll
        for (int ks = 0; ks < 256; ks += 16) {
            uint32_t af[2][4];
#pragma unroll
            for (int mi = 0; mi < 2; mi++) {
                uint32_t addr = s2u(&As[(mw + mi * 16 + (lane & 15)) * 264 + ks + (lane >> 4) * 8]);
                ldmA(af[mi], addr);
            }
#pragma unroll
            for (int nf = 0; nf < 4; nf++) {
                uint32_t bf[4];
                uint32_t addr = s2u(&Bs[(ks + ((lane >> 3) & 1) * 8 + (lane & 7)) * 264 +
                                        nw + nf * 16 + (lane >> 4) * 8]);
                ldmT(bf, addr);
#pragma unroll
                for (int mi = 0; mi < 2; mi++) {
                    mma16816(acc[mi][nf * 2], af[mi], bf);
                    mma16816(acc[mi][nf * 2 + 1], af[mi], bf + 2);
                }
            }
        }

        int m0 = ti * 64;
        uint32_t* h1u = (uint32_t*)g_h1b;
#pragma unroll
        for (int mi = 0; mi < 2; mi++) {
#pragma unroll
            for (int nf = 0; nf < 8; nf++) {
                int col = nw + nf * 8 + (lane & 3) * 2;
                float bx = b1[col], by = b1[col + 1];
                int row = m0 + mw + mi * 16 + (lane >> 2);
                if (row < NN)
                    h1u[((size_t)row * HID + col) >> 1] =
                        pkbf(fmaxf(acc[mi][nf][0] + bx, 0.f), fmaxf(acc[mi][nf][1] + by, 0.f));
                int row2 = row + 8;
                if (row2 < NN)
                    h1u[((size_t)row2 * HID + col) >> 1] =
                        pkbf(fmaxf(acc[mi][nf][2] + bx, 0.f), fmaxf(acc[mi][nf][3] + by, 0.f));
            }
        }
    }
}

// ------- GEMM2 (bf16 mma) + fused pool: Qa = coef^T @ h1, P = segsum(h1) -------
__global__ void __launch_bounds__(256) gemm2_k(const int* __restrict__ batch) {
    __shared__ __align__(16) __nv_bfloat16 Ks[32 * 72];
    __shared__ __align__(16) __nv_bfloat16 Bs[32 * 264];
    __shared__ int sbatch[32];
    int tid = threadIdx.x;
    int wid = tid >> 5, lane = tid & 31;
    int nb = blockIdx.x * G2CH;
    int n0w = wid * 32;

    float acc[4][4][4];
#pragma unroll
    for (int i = 0; i < 4; i++)
#pragma unroll
        for (int j = 0; j < 4; j++)
#pragma unroll
            for (int q = 0; q < 4; q++) acc[i][j][q] = 0.f;

    int cnode = tid >> 3;
    int cg = (tid & 7) * 8;

    float4 cf0, cf1;
    uint4 hb[4];

    {
        size_t base = (size_t)(nb + cnode) * NG + cg;
        cf0 = *(const float4*)&g_coef[base];
        cf1 = *(const float4*)&g_coef[base + 4];
#pragma unroll
        for (int j = 0; j < 4; j++) {
            int c = tid + 256 * j;
            int row = c >> 5, col = (c & 31) * 8;
            hb[j] = *(const uint4*)&g_h1b[(size_t)(nb + row) * HID + col];
        }
    }

    int curg = batch[nb];
    float psum = 0.f;

    for (int s = 0; s < 25; s++) {
        __syncthreads();
        {
            uint4 kv = make_uint4(pkbf(cf0.x, cf0.y), pkbf(cf0.z, cf0.w),
                                  pkbf(cf1.x, cf1.y), pkbf(cf1.z, cf1.w));
            *(uint4*)&Ks[cnode * 72 + cg] = kv;
#pragma unroll
            for (int j = 0; j < 4; j++) {
                int c = tid + 256 * j;
                int row = c >> 5, col = (c & 31) * 8;
                *(uint4*)&Bs[row * 264 + col] = hb[j];
            }
            if (tid < 32) sbatch[tid] = batch[nb + s * 32 + tid];
        }
        __syncthreads();

        if (s + 1 < 25) {
            int kb = nb + (s + 1) * 32;
            size_t base = (size_t)(kb + cnode) * NG + cg;
            cf0 = *(const float4*)&g_coef[base];
            cf1 = *(const float4*)&g_coef[base + 4];
#pragma unroll
            for (int j = 0; j < 4; j++) {
                int c = tid + 256 * j;
                int row = c >> 5, col = (c & 31) * 8;
                hb[j] = *(const uint4*)&g_h1b[(size_t)(kb + row) * HID + col];
            }
        }

#pragma unroll
        for (int ks = 0; ks < 32; ks += 16) {
            uint32_t af[4][4];
#pragma unroll
            for (int mi = 0; mi < 4; mi++) {
                uint32_t addr = s2u(&Ks[(ks + ((lane >> 4) & 1) * 8 + (lane & 7)) * 72 +
                                        mi * 16 + ((lane >> 3) & 1) * 8]);
                ldmT(af[mi], addr);
            }
#pragma unroll
            for (int nf = 0; nf < 2; nf++) {
                uint32_t bf[4];
                uint32_t addr = s2u(&Bs[(ks + ((lane >> 3) & 1) * 8 + (lane & 7)) * 264 +
                                        n0w + nf * 16 + (lane >> 4) * 8]);
                ldmT(bf, addr);
#pragma unroll
                for (int mi = 0; mi < 4; mi++) {
                    mma16816(acc[mi][nf * 2], af[mi], bf);
                    mma16816(acc[mi][nf * 2 + 1], af[mi], bf + 2);
                }
            }
        }

        for (int r = 0; r < 32; r++) {
            int g = sbatch[r];
            float v = __bfloat162float(Bs[r * 264 + tid]);
            if (g != curg) {
                atomicAdd(&g_P[curg * HID + tid], psum);
                psum = 0.f;
                curg = g;
            }
            psum += v;
        }
    }
    atomicAdd(&g_P[curg * HID + tid], psum);

#pragma unroll
    for (int mi = 0; mi < 4; mi++) {
#pragma unroll
        for (int nf = 0; nf < 4; nf++) {
            int col = n0w + nf * 8 + (lane & 3) * 2;
            int row = mi * 16 + (lane >> 2);
            atomicAdd(&g_Qa[row * HID + col], acc[mi][nf][0]);
            atomicAdd(&g_Qa[row * HID + col + 1], acc[mi][nf][1]);
            atomicAdd(&g_Qa[(row + 8) * HID + col], acc[mi][nf][2]);
            atomicAdd(&g_Qa[(row + 8) * HID + col + 1], acc[mi][nf][3]);
        }
    }
}

// --------------------------- final: layer2 fold + pool + MLP head ---------------------------
__global__ void final_k(const float* __restrict__ gattr,
                        const float* __restrict__ W2l, const float* __restrict__ b2,
                        const float* __restrict__ W2r,
                        const float* __restrict__ Wf1, const float* __restrict__ bf1,
                        const float* __restrict__ Wf2, const float* __restrict__ bf2,
                        float* __restrict__ out) {
    __shared__ float q[HID], p[HID], pooled[HID], red[HID];
    int g = blockIdx.x, j = threadIdx.x;
    q[j] = g_Qa[g * HID + j];
    p[j] = g_P[g * HID + j];
    __syncthreads();
    float acc = 0.f;
    for (int k = 0; k < HID; k++)
        acc += q[k] * W2l[k * HID + j] + p[k] * W2r[k * HID + j];
    pooled[j] = g_invng[g] * acc + b2[j];
    __syncthreads();
    float a2 = bf1[j];
    for (int k = 0; k < HID; k++)
        a2 += pooled[k] * Wf1[k * HID + j];
    for (int a = 0; a < 8; a++)
        a2 += gattr[g * 8 + a] * Wf1[(HID + a) * HID + j];
    float t1 = fmaxf(a2, 0.f);
    red[j] = t1 * Wf2[j];
    __syncthreads();
    for (int s = 128; s > 0; s >>= 1) {
        if (j < s) red[j] += red[j + s];
        __syncthreads();
    }
    if (j == 0) out[g] = red[0] + bf2[0];
}

// --------------------------- launch ---------------------------
extern "C" void kernel_launch(void* const* d_in, const int* in_sizes, int n_in,
                              void* d_out, int out_size) {
    const float* x = (const float*)d_in[0];
    const int* ei = (const int*)d_in[1];
    const int* batch = (const int*)d_in[2];
    const float* gattr = (const float*)d_in[3];
    const float* W1l = (const float*)d_in[4];
    const float* b1  = (const float*)d_in[5];
    const float* W1r = (const float*)d_in[6];
    const float* W2l = (const float*)d_in[7];
    const float* b2  = (const float*)d_in[8];
    const float* W2r = (const float*)d_in[9];
    const float* Wf1 = (const float*)d_in[10];
    const float* bf1 = (const float*)d_in[11];
    const float* Wf2 = (const float*)d_in[12];
    const float* bf2 = (const float*)d_in[13];
    float* out = (float*)d_out;

    static cudaStream_t sA = nullptr;
    static cudaEvent_t evFork = nullptr, evJoin = nullptr;
    if (sA == nullptr) {
        cudaStreamCreateWithFlags(&sA, cudaStreamNonBlocking);
        cudaEventCreateWithFlags(&evFork, cudaEventDisableTiming);
        cudaEventCreateWithFlags(&evJoin, cudaEventDisableTiming);
        const int S = (256 * 264 + 64 * 264) * (int)sizeof(__nv_bfloat16);
        cudaFuncSetAttribute(gemm1_k, cudaFuncAttributeMaxDynamicSharedMemorySize, S);
    }
    const int SMEM1 = (256 * 264 + 64 * 264) * (int)sizeof(__nv_bfloat16);  // 168960 B

    initA_k<<<1024, 256>>>(x, W1l, W1r);
    initB_k<<<256, 256>>>();
    cnt_k<<<1563, 256>>>(ei, batch);
    scan1_k<<<NB1, 256>>>();
    scan23_k<<<NB1, 256>>>(batch);
    place_k<<<(NE / 4 + 255) / 256, 256>>>(ei);

    // fork: coef atomics (L2-latency-bound, issue 2.9%) overlap agg1 (issue-bound)
    // and gemm1 (tensor-bound, smem-resident weights). gemm2 is first coef consumer.
    cudaEventRecord(evFork, 0);
    cudaStreamWaitEvent(sA, evFork, 0);
    coef_k<<<(NE / 4 + 255) / 256, 256, 0, sA>>>(ei);
    cudaEventRecord(evJoin, sA);

    agg1_k<<<(NN * 32 + 255) / 256, 256>>>();
    gemm1_k<<<G1BLK, 256, SMEM1>>>(b1);

    cudaStreamWaitEvent(0, evJoin, 0);
    gemm2_k<<<G2BLK, 256>>>(batch);
    final_k<<<NG, 256>>>(gattr, W2l, b2, W2r, Wf1, bf1, Wf2, bf2, out);
}